// round 7
// baseline (speedup 1.0000x reference)
#include <cuda_runtime.h>
#include <cuda_bf16.h>
#include <float.h>

#define NROWS 260000
#define NCLS  1024
#define NBINS 20
#define BINSZ 13000
#define NBND  19   /* interior bin boundaries at ranks 13000*b, b=1..19 */

// ---- static device scratch (no allocations allowed) ----
__device__ unsigned int g_keys[NROWS];   // conf float bits (positive float -> uint order == float order)
__device__ unsigned int g_vals[NROWS];   // accuracy 0/1
__device__ int          g_is64;

// zeroed each launch with one memsetAsync (members are contiguous)
struct Scratch {
    unsigned int       chist[65536];          // coarse histogram of key>>16
    unsigned int       fine[NBND * 65536];    // per-boundary-slot histogram of key&0xFFFF
    unsigned long long sumc[NBINS];           // conf * 2^32 fixed point (deterministic int atomics)
    unsigned int       suma[NBINS];           // accuracy counts
    unsigned int       tiecnt;
};
__device__ Scratch S;

__device__ unsigned int g_bnd_bucket[NBND];   // coarse bucket containing boundary b
__device__ unsigned int g_bnd_Fc[NBND];       // #keys in buckets strictly below
__device__ unsigned int g_bnd_key[NBND];      // exact 32-bit boundary key K_b
__device__ unsigned int g_bnd_F[NBND];        // F(K_b) = #keys < K_b
__device__ unsigned int g_tie_idx[NROWS];     // indices of elements with key == some K_b
__device__ unsigned int g_tie_meta[NROWS];    // (boundary_slot<<1) | acc

// Detect whether labels buffer is int64 (odd 32-bit words all zero) or int32.
__global__ void detect_kernel(const int* __restrict__ labels32) {
    unsigned mask = __ballot_sync(0xffffffffu, labels32[2 * threadIdx.x + 1] == 0);
    if (threadIdx.x == 0) g_is64 = (mask == 0xffffffffu) ? 1 : 0;
}

// Warp-per-row: 8x LDG.128 per lane (MLP_p1=8), pure warp-shuffle reductions.
// conf = 1/sum(exp(x-max)) == max softmax. argmax = first occurrence.
// Lane 0 also feeds the coarse histogram (hidden under HBM-bound mainloop).
__global__ void __launch_bounds__(256) row_kernel(const float* __restrict__ logits,
                                                  const void* __restrict__ labels) {
    const int warp = threadIdx.x >> 5;
    const int lane = threadIdx.x & 31;
    const int row  = blockIdx.x * 8 + warp;

    const float4* base = reinterpret_cast<const float4*>(logits) + (size_t)row * (NCLS / 4);
    float4 v[8];
    #pragma unroll
    for (int i = 0; i < 8; i++) v[i] = __ldcs(&base[i * 32 + lane]);

    float m = -FLT_MAX; int mi = 0x7fffffff;
    #pragma unroll
    for (int i = 0; i < 8; i++) {
        const int b = (i * 32 + lane) * 4;
        if (v[i].x > m) { m = v[i].x; mi = b;     }
        if (v[i].y > m) { m = v[i].y; mi = b + 1; }
        if (v[i].z > m) { m = v[i].z; mi = b + 2; }
        if (v[i].w > m) { m = v[i].w; mi = b + 3; }
    }
    #pragma unroll
    for (int o = 16; o > 0; o >>= 1) {
        float om = __shfl_xor_sync(0xffffffffu, m,  o);
        int   oi = __shfl_xor_sync(0xffffffffu, mi, o);
        if (om > m || (om == m && oi < mi)) { m = om; mi = oi; }
    }

    float e = 0.0f;
    #pragma unroll
    for (int i = 0; i < 8; i++) {
        e += __expf(v[i].x - m) + __expf(v[i].y - m)
           + __expf(v[i].z - m) + __expf(v[i].w - m);
    }
    #pragma unroll
    for (int o = 16; o > 0; o >>= 1) e += __shfl_xor_sync(0xffffffffu, e, o);

    if (lane == 0) {
        const float conf = 1.0f / e;
        const unsigned key = __float_as_uint(conf);
        g_keys[row] = key;
        const int lab = g_is64 ? (int)((const long long*)labels)[row]
                               : ((const int*)labels)[row];
        g_vals[row] = (mi == lab) ? 1u : 0u;
        atomicAdd(&S.chist[key >> 16], 1u);
    }
}

// 1 block, 1024 threads: exclusive scan of the 2^16 coarse histogram; locate the
// coarse bucket containing each boundary rank r_b = 13000*b.
__global__ void __launch_bounds__(1024) scan_kernel() {
    __shared__ unsigned int warp_sums[32];
    const int t = threadIdx.x, lane = t & 31, w = t >> 5;

    unsigned int sum = 0;
    for (int k = 0; k < 64; k++) sum += S.chist[t * 64 + k];

    unsigned int x = sum;
    #pragma unroll
    for (int o = 1; o < 32; o <<= 1) {
        unsigned y = __shfl_up_sync(0xffffffffu, x, o);
        if (lane >= o) x += y;
    }
    if (lane == 31) warp_sums[w] = x;
    __syncthreads();
    if (w == 0) {
        unsigned v = warp_sums[lane];
        #pragma unroll
        for (int o = 1; o < 32; o <<= 1) {
            unsigned y = __shfl_up_sync(0xffffffffu, v, o);
            if (lane >= o) v += y;
        }
        warp_sums[lane] = v;
    }
    __syncthreads();
    const unsigned int P = x + (w > 0 ? warp_sums[w - 1] : 0) - sum;  // exclusive prefix
    const unsigned int hi = P + sum;

    unsigned r0 = ((P + BINSZ - 1) / BINSZ) * BINSZ;
    if (r0 < BINSZ) r0 = BINSZ;
    for (unsigned r = r0; r < hi && r <= (unsigned)(NBND * BINSZ); r += BINSZ) {
        unsigned cum = P;
        for (int k = 0; k < 64; k++) {
            const unsigned h = S.chist[t * 64 + k];
            if (cum <= r && r < cum + h) {
                const int b = r / BINSZ - 1;
                g_bnd_bucket[b] = t * 64 + k;
                g_bnd_Fc[b] = cum;
            }
            cum += h;
        }
    }
}

// One pass over keys: fine histogram (low 16 bits) for elements whose coarse
// bucket contains a boundary. Slot = first boundary with that bucket.
__global__ void __launch_bounds__(256) fine_kernel() {
    __shared__ unsigned int bkt[NBND];
    if (threadIdx.x < NBND) bkt[threadIdx.x] = g_bnd_bucket[threadIdx.x];
    __syncthreads();
    for (int i = blockIdx.x * 256 + threadIdx.x; i < NROWS; i += gridDim.x * 256) {
        const unsigned key = g_keys[i];
        const unsigned top = key >> 16;
        int slot = -1;
        #pragma unroll
        for (int b = 0; b < NBND; b++)
            if (slot < 0 && bkt[b] == top) slot = b;
        if (slot >= 0) atomicAdd(&S.fine[slot * 65536 + (key & 0xFFFFu)], 1u);
    }
}

// grid=19: each block resolves the exact 32-bit boundary key and F(K_b).
__global__ void __launch_bounds__(256) resolve_kernel() {
    __shared__ int s_slot;
    __shared__ unsigned s_bucket, s_Fc;
    __shared__ unsigned warp_sums[8];
    const int b = blockIdx.x, t = threadIdx.x, lane = t & 31, w = t >> 5;

    if (t == 0) {
        const unsigned bucket = g_bnd_bucket[b];
        s_bucket = bucket;
        s_Fc = g_bnd_Fc[b];
        int slot = b;
        for (int i = 0; i < NBND; i++)
            if (g_bnd_bucket[i] == bucket) { slot = i; break; }
        s_slot = slot;
    }
    __syncthreads();
    const unsigned* F = &S.fine[s_slot * 65536];

    unsigned sum = 0;
    for (int k = 0; k < 256; k++) sum += F[t * 256 + k];

    unsigned x = sum;
    #pragma unroll
    for (int o = 1; o < 32; o <<= 1) {
        unsigned y = __shfl_up_sync(0xffffffffu, x, o);
        if (lane >= o) x += y;
    }
    if (lane == 31) warp_sums[w] = x;
    __syncthreads();
    if (w == 0 && lane < 8) {
        unsigned v = warp_sums[lane];
        #pragma unroll
        for (int o = 1; o < 8; o <<= 1) {
            unsigned y = __shfl_up_sync(0x000000ffu, v, o);
            if (lane >= o) v += y;
        }
        warp_sums[lane] = v;
    }
    __syncthreads();
    const unsigned P = x + (w > 0 ? warp_sums[w - 1] : 0) - sum;

    const unsigned r = (unsigned)(b + 1) * BINSZ;
    unsigned cum = s_Fc + P;
    if (r >= cum && r < cum + sum) {
        for (int k = 0; k < 256; k++) {
            const unsigned h = F[t * 256 + k];
            if (cum <= r && r < cum + h) {
                g_bnd_key[b] = (s_bucket << 16) | (unsigned)(t * 256 + k);
                g_bnd_F[b] = cum;
            }
            cum += h;
        }
    }
}

// One pass: bin = #{boundaries with key >= K_b} (ties go to the upper bin,
// corrected in finalize). Conf summed as exact u64 fixed point (deterministic).
__global__ void __launch_bounds__(256) binsum_kernel() {
    __shared__ unsigned long long sC[NBINS];
    __shared__ unsigned int       sA[NBINS];
    __shared__ unsigned int       K[NBND];
    const int t = threadIdx.x;
    if (t < NBINS) { sC[t] = 0ull; sA[t] = 0u; }
    if (t < NBND)  K[t] = g_bnd_key[t];
    __syncthreads();

    for (int i = blockIdx.x * 256 + t; i < NROWS; i += gridDim.x * 256) {
        const unsigned key = g_keys[i];
        const unsigned acc = g_vals[i];
        int bin = 0, tie = -1;
        #pragma unroll
        for (int b = 0; b < NBND; b++) {
            bin += (key >= K[b]);
            if (tie < 0 && key == K[b]) tie = b;
        }
        const unsigned long long cfix =
            (unsigned long long)((double)__uint_as_float(key) * 4294967296.0);
        atomicAdd(&sC[bin], cfix);
        atomicAdd(&sA[bin], acc);
        if (tie >= 0) {
            const unsigned p = atomicAdd(&S.tiecnt, 1u);
            if (p < (unsigned)NROWS) {
                g_tie_idx[p]  = (unsigned)i;
                g_tie_meta[p] = ((unsigned)tie << 1) | acc;
            }
        }
    }
    __syncthreads();
    if (t < NBINS) {
        atomicAdd(&S.sumc[t], sC[t]);
        atomicAdd(&S.suma[t], sA[t]);
    }
}

// Tie correction (stable-sort semantics: smallest original indices go below the
// boundary) + ce/ece/mce. All corrections use integer counts -> deterministic.
__global__ void __launch_bounds__(256) finalize_kernel(float* __restrict__ out) {
    __shared__ unsigned int mv[NBND];
    __shared__ unsigned int K[NBND], Fb[NBND];
    const int t = threadIdx.x;
    if (t < NBND) { mv[t] = 0u; K[t] = g_bnd_key[t]; Fb[t] = g_bnd_F[t]; }
    __syncthreads();

    unsigned T = S.tiecnt;
    if (T > (unsigned)NROWS) T = NROWS;
    for (unsigned e = t; e < T; e += 256) {
        const unsigned meta = g_tie_meta[e];
        const unsigned b0 = meta >> 1, acc = meta & 1u;
        const unsigned idx = g_tie_idx[e];
        unsigned j = 0;  // index-rank within this key group (same b0 <=> same key)
        for (unsigned e2 = 0; e2 < T; e2++)
            if ((g_tie_meta[e2] >> 1) == b0 && g_tie_idx[e2] < idx) j++;
        const unsigned mykey = K[b0];
        for (int b = 0; b < NBND; b++) {
            if (K[b] == mykey) {
                const unsigned nm = (unsigned)(b + 1) * BINSZ - Fb[b];  // move-down count
                if (j < nm) atomicAdd(&mv[b], acc);
            }
        }
    }
    __syncthreads();

    if (t == 0) {
        double sc[NBINS], sa[NBINS];
        for (int b = 0; b < NBINS; b++) {
            sc[b] = (double)S.sumc[b] * (1.0 / 4294967296.0);
            sa[b] = (double)S.suma[b];
        }
        for (int b = 0; b < NBND; b++) {
            const unsigned nm = (unsigned)(b + 1) * BINSZ - Fb[b];
            if (nm > 0) {
                const double c = (double)__uint_as_float(K[b]) * (double)nm;
                sc[b + 1] -= c;  sc[b] += c;
                const double a = (double)mv[b];
                sa[b + 1] -= a;  sa[b] += a;
            }
        }
        double ece = 0.0, mce = 0.0;
        for (int b = 0; b < NBINS; b++) {
            const double ce = fabs(sc[b] - sa[b]) / (double)BINSZ;
            ece += ce;
            if (ce > mce) mce = ce;
        }
        out[0] = (float)(ece / (double)NBINS);
        out[1] = (float)mce;
    }
}

extern "C" void kernel_launch(void* const* d_in, const int* in_sizes, int n_in,
                              void* d_out, int out_size) {
    const float* logits = (const float*)d_in[0];
    const void*  labels = d_in[1];
    float* out = (float*)d_out;

    void* s_addr;
    cudaGetSymbolAddress(&s_addr, S);
    cudaMemsetAsync(s_addr, 0, sizeof(Scratch), (cudaStream_t)0);

    detect_kernel<<<1, 32>>>((const int*)labels);
    row_kernel<<<NROWS / 8, 256>>>(logits, labels);
    scan_kernel<<<1, 1024>>>();
    fine_kernel<<<512, 256>>>();
    resolve_kernel<<<NBND, 256>>>();
    binsum_kernel<<<260, 256>>>();
    finalize_kernel<<<1, 256>>>(out);
}

// round 8
// speedup vs baseline: 1.5623x; 1.5623x over previous
#include <cuda_runtime.h>
#include <cuda_bf16.h>
#include <float.h>

#define NROWS 260000
#define NCLS  1024
#define NBINS 20
#define BINSZ 13000
#define NBND  19          /* interior boundaries at ranks 13000*b, b=1..19 */
#define KBASE 0x3A800000u /* float bits of 2^-10 = 1/1024 <= conf <= 1 -> key' < 2^27 */
#define NCOARSE 8192      /* key' >> 14 */
#define NFINE   16384     /* key' & 0x3FFF */

// ---- static device scratch (no allocations allowed) ----
__device__ unsigned int g_keys[NROWS];   // conf float bits (positive -> uint order == float order)
__device__ unsigned int g_vals[NROWS];   // accuracy 0/1
__device__ int          g_is64;

// zeroed each launch with one memsetAsync (contiguous)
struct Scratch {
    unsigned int       chist[NCOARSE];        // coarse histogram of key'>>14
    unsigned int       fine[NBND * NFINE];    // per-boundary-slot histogram of key'&0x3FFF
    unsigned long long sumc[NBINS];           // conf * 2^32 fixed point (deterministic)
    unsigned int       suma[NBINS];           // accuracy counts
    unsigned int       tiecnt;
};
__device__ Scratch S;

__device__ unsigned int g_bnd_bucket[NBND];   // coarse bucket containing boundary b
__device__ unsigned int g_bnd_Fc[NBND];       // #keys in coarse buckets strictly below
__device__ unsigned int g_bnd_key[NBND];      // boundary key in key' space
__device__ unsigned int g_bnd_F[NBND];        // F(K_b) = #keys' < K_b
__device__ unsigned int g_tie_idx[NROWS];     // indices of elements with key' == some K_b
__device__ unsigned int g_tie_meta[NROWS];    // (boundary_slot<<1) | acc

__device__ __forceinline__ unsigned kprime(unsigned key) {
    return (key > KBASE) ? (key - KBASE) : 0u;
}

// Detect whether labels buffer is int64 (odd 32-bit words all zero) or int32.
__global__ void detect_kernel(const int* __restrict__ labels32) {
    unsigned mask = __ballot_sync(0xffffffffu, labels32[2 * threadIdx.x + 1] == 0);
    if (threadIdx.x == 0) g_is64 = (mask == 0xffffffffu) ? 1 : 0;
}

// Warp-per-row: 8x LDG.128 per lane (MLP_p1=8), pure warp-shuffle reductions.
// NO atomics here (R7 lesson: the histogram hotspot stalled the HBM-bound loop).
__global__ void __launch_bounds__(256) row_kernel(const float* __restrict__ logits,
                                                  const void* __restrict__ labels) {
    const int warp = threadIdx.x >> 5;
    const int lane = threadIdx.x & 31;
    const int row  = blockIdx.x * 8 + warp;

    const float4* base = reinterpret_cast<const float4*>(logits) + (size_t)row * (NCLS / 4);
    float4 v[8];
    #pragma unroll
    for (int i = 0; i < 8; i++) v[i] = __ldcs(&base[i * 32 + lane]);

    float m = -FLT_MAX; int mi = 0x7fffffff;
    #pragma unroll
    for (int i = 0; i < 8; i++) {
        const int b = (i * 32 + lane) * 4;
        if (v[i].x > m) { m = v[i].x; mi = b;     }
        if (v[i].y > m) { m = v[i].y; mi = b + 1; }
        if (v[i].z > m) { m = v[i].z; mi = b + 2; }
        if (v[i].w > m) { m = v[i].w; mi = b + 3; }
    }
    #pragma unroll
    for (int o = 16; o > 0; o >>= 1) {
        float om = __shfl_xor_sync(0xffffffffu, m,  o);
        int   oi = __shfl_xor_sync(0xffffffffu, mi, o);
        if (om > m || (om == m && oi < mi)) { m = om; mi = oi; }
    }

    float e = 0.0f;
    #pragma unroll
    for (int i = 0; i < 8; i++) {
        e += __expf(v[i].x - m) + __expf(v[i].y - m)
           + __expf(v[i].z - m) + __expf(v[i].w - m);
    }
    #pragma unroll
    for (int o = 16; o > 0; o >>= 1) e += __shfl_xor_sync(0xffffffffu, e, o);

    if (lane == 0) {
        const float conf = 1.0f / e;
        g_keys[row] = __float_as_uint(conf);
        const int lab = g_is64 ? (int)((const long long*)labels)[row]
                               : ((const int*)labels)[row];
        g_vals[row] = (mi == lab) ? 1u : 0u;
    }
}

// Shared-memory privatized coarse histogram (8192 buckets = 32 KB smem).
__global__ void __launch_bounds__(256) hist_kernel() {
    __shared__ unsigned int sh[NCOARSE];
    for (int i = threadIdx.x; i < NCOARSE; i += 256) sh[i] = 0u;
    __syncthreads();
    for (int i = blockIdx.x * 256 + threadIdx.x; i < NROWS; i += gridDim.x * 256)
        atomicAdd(&sh[kprime(g_keys[i]) >> 14], 1u);
    __syncthreads();
    for (int i = threadIdx.x; i < NCOARSE; i += 256) {
        const unsigned c = sh[i];
        if (c) atomicAdd(&S.chist[i], c);
    }
}

// 1 block, 256 threads: scan 8192 coarse counters; locate boundary buckets.
__global__ void __launch_bounds__(256) scan_kernel() {
    __shared__ unsigned int warp_sums[8];
    const int t = threadIdx.x, lane = t & 31, w = t >> 5;

    unsigned int sum = 0;
    #pragma unroll
    for (int k = 0; k < 32; k++) sum += S.chist[t * 32 + k];

    unsigned int x = sum;
    #pragma unroll
    for (int o = 1; o < 32; o <<= 1) {
        unsigned y = __shfl_up_sync(0xffffffffu, x, o);
        if (lane >= o) x += y;
    }
    if (lane == 31) warp_sums[w] = x;
    __syncthreads();
    if (w == 0 && lane < 8) {
        unsigned v = warp_sums[lane];
        #pragma unroll
        for (int o = 1; o < 8; o <<= 1) {
            unsigned y = __shfl_up_sync(0x000000ffu, v, o);
            if (lane >= o) v += y;
        }
        warp_sums[lane] = v;
    }
    __syncthreads();
    const unsigned int P = x + (w > 0 ? warp_sums[w - 1] : 0) - sum;  // exclusive prefix
    const unsigned int hi = P + sum;

    unsigned r0 = ((P + BINSZ - 1) / BINSZ) * BINSZ;
    if (r0 < BINSZ) r0 = BINSZ;
    for (unsigned r = r0; r < hi && r <= (unsigned)(NBND * BINSZ); r += BINSZ) {
        unsigned cum = P;
        for (int k = 0; k < 32; k++) {
            const unsigned h = S.chist[t * 32 + k];
            if (cum <= r && r < cum + h) {
                const int b = r / BINSZ - 1;
                g_bnd_bucket[b] = t * 32 + k;
                g_bnd_Fc[b] = cum;
            }
            cum += h;
        }
    }
}

// One pass: fine histogram (low 14 bits) for elements whose coarse bucket holds
// a boundary. Slot = first boundary with that bucket.
__global__ void __launch_bounds__(256) fine_kernel() {
    __shared__ unsigned int bkt[NBND];
    if (threadIdx.x < NBND) bkt[threadIdx.x] = g_bnd_bucket[threadIdx.x];
    __syncthreads();
    for (int i = blockIdx.x * 256 + threadIdx.x; i < NROWS; i += gridDim.x * 256) {
        const unsigned kp = kprime(g_keys[i]);
        const unsigned top = kp >> 14;
        int slot = -1;
        #pragma unroll
        for (int b = 0; b < NBND; b++)
            if (slot < 0 && bkt[b] == top) slot = b;
        if (slot >= 0) atomicAdd(&S.fine[slot * NFINE + (kp & 0x3FFFu)], 1u);
    }
}

// grid=19: resolve the exact key'-space boundary key and F(K_b).
__global__ void __launch_bounds__(256) resolve_kernel() {
    __shared__ int s_slot;
    __shared__ unsigned s_bucket, s_Fc;
    __shared__ unsigned warp_sums[8];
    const int b = blockIdx.x, t = threadIdx.x, lane = t & 31, w = t >> 5;

    if (t == 0) {
        const unsigned bucket = g_bnd_bucket[b];
        s_bucket = bucket;
        s_Fc = g_bnd_Fc[b];
        int slot = b;
        for (int i = 0; i < NBND; i++)
            if (g_bnd_bucket[i] == bucket) { slot = i; break; }
        s_slot = slot;
    }
    __syncthreads();
    const unsigned* F = &S.fine[s_slot * NFINE];

    unsigned sum = 0;
    #pragma unroll 8
    for (int k = 0; k < 64; k++) sum += F[t * 64 + k];

    unsigned x = sum;
    #pragma unroll
    for (int o = 1; o < 32; o <<= 1) {
        unsigned y = __shfl_up_sync(0xffffffffu, x, o);
        if (lane >= o) x += y;
    }
    if (lane == 31) warp_sums[w] = x;
    __syncthreads();
    if (w == 0 && lane < 8) {
        unsigned v = warp_sums[lane];
        #pragma unroll
        for (int o = 1; o < 8; o <<= 1) {
            unsigned y = __shfl_up_sync(0x000000ffu, v, o);
            if (lane >= o) v += y;
        }
        warp_sums[lane] = v;
    }
    __syncthreads();
    const unsigned P = x + (w > 0 ? warp_sums[w - 1] : 0) - sum;

    const unsigned r = (unsigned)(b + 1) * BINSZ;
    unsigned cum = s_Fc + P;
    if (r >= cum && r < cum + sum) {
        for (int k = 0; k < 64; k++) {
            const unsigned h = F[t * 64 + k];
            if (cum <= r && r < cum + h) {
                g_bnd_key[b] = (s_bucket << 14) | (unsigned)(t * 64 + k);  // key' space
                g_bnd_F[b] = cum;
            }
            cum += h;
        }
    }
}

// One pass: bin = #{boundaries with key' >= K_b} (ties to upper bin, corrected
// in finalize). Conf summed as exact u64 fixed point (order-independent).
__global__ void __launch_bounds__(256) binsum_kernel() {
    __shared__ unsigned long long sC[NBINS];
    __shared__ unsigned int       sA[NBINS];
    __shared__ unsigned int       K[NBND];
    const int t = threadIdx.x;
    if (t < NBINS) { sC[t] = 0ull; sA[t] = 0u; }
    if (t < NBND)  K[t] = g_bnd_key[t];
    __syncthreads();

    for (int i = blockIdx.x * 256 + t; i < NROWS; i += gridDim.x * 256) {
        const unsigned key = g_keys[i];
        const unsigned kp  = kprime(key);
        const unsigned acc = g_vals[i];
        int bin = 0, tie = -1;
        #pragma unroll
        for (int b = 0; b < NBND; b++) {
            bin += (kp >= K[b]);
            if (tie < 0 && kp == K[b]) tie = b;
        }
        const unsigned long long cfix =
            (unsigned long long)((double)__uint_as_float(key) * 4294967296.0);
        atomicAdd(&sC[bin], cfix);
        atomicAdd(&sA[bin], acc);
        if (tie >= 0) {
            const unsigned p = atomicAdd(&S.tiecnt, 1u);
            if (p < (unsigned)NROWS) {
                g_tie_idx[p]  = (unsigned)i;
                g_tie_meta[p] = ((unsigned)tie << 1) | acc;
            }
        }
    }
    __syncthreads();
    if (t < NBINS) {
        atomicAdd(&S.sumc[t], sC[t]);
        atomicAdd(&S.suma[t], sA[t]);
    }
}

// Tie correction (stable-sort semantics: smallest original indices go below the
// boundary) + ce/ece/mce. Integer counts -> deterministic.
__global__ void __launch_bounds__(256) finalize_kernel(float* __restrict__ out) {
    __shared__ unsigned int mv[NBND];
    __shared__ unsigned int K[NBND], Fb[NBND];
    const int t = threadIdx.x;
    if (t < NBND) { mv[t] = 0u; K[t] = g_bnd_key[t]; Fb[t] = g_bnd_F[t]; }
    __syncthreads();

    unsigned T = S.tiecnt;
    if (T > (unsigned)NROWS) T = NROWS;
    for (unsigned e = t; e < T; e += 256) {
        const unsigned meta = g_tie_meta[e];
        const unsigned b0 = meta >> 1, acc = meta & 1u;
        const unsigned idx = g_tie_idx[e];
        unsigned j = 0;  // index-rank within this key group
        for (unsigned e2 = 0; e2 < T; e2++)
            if ((g_tie_meta[e2] >> 1) == b0 && g_tie_idx[e2] < idx) j++;
        const unsigned mykey = K[b0];
        for (int b = 0; b < NBND; b++) {
            if (K[b] == mykey) {
                const unsigned nm = (unsigned)(b + 1) * BINSZ - Fb[b];  // move-down count
                if (j < nm) atomicAdd(&mv[b], acc);
            }
        }
    }
    __syncthreads();

    if (t == 0) {
        double sc[NBINS], sa[NBINS];
        for (int b = 0; b < NBINS; b++) {
            sc[b] = (double)S.sumc[b] * (1.0 / 4294967296.0);
            sa[b] = (double)S.suma[b];
        }
        for (int b = 0; b < NBND; b++) {
            const unsigned nm = (unsigned)(b + 1) * BINSZ - Fb[b];
            if (nm > 0) {
                const double c = (double)__uint_as_float(K[b] + KBASE) * (double)nm;
                sc[b + 1] -= c;  sc[b] += c;
                const double a = (double)mv[b];
                sa[b + 1] -= a;  sa[b] += a;
            }
        }
        double ece = 0.0, mce = 0.0;
        for (int b = 0; b < NBINS; b++) {
            const double ce = fabs(sc[b] - sa[b]) / (double)BINSZ;
            ece += ce;
            if (ce > mce) mce = ce;
        }
        out[0] = (float)(ece / (double)NBINS);
        out[1] = (float)mce;
    }
}

extern "C" void kernel_launch(void* const* d_in, const int* in_sizes, int n_in,
                              void* d_out, int out_size) {
    const float* logits = (const float*)d_in[0];
    const void*  labels = d_in[1];
    float* out = (float*)d_out;

    void* s_addr;
    cudaGetSymbolAddress(&s_addr, S);
    cudaMemsetAsync(s_addr, 0, sizeof(Scratch), (cudaStream_t)0);

    detect_kernel<<<1, 32>>>((const int*)labels);
    row_kernel<<<NROWS / 8, 256>>>(logits, labels);
    hist_kernel<<<64, 256>>>();
    scan_kernel<<<1, 256>>>();
    fine_kernel<<<260, 256>>>();
    resolve_kernel<<<NBND, 256>>>();
    binsum_kernel<<<260, 256>>>();
    finalize_kernel<<<1, 256>>>(out);
}